// round 1
// baseline (speedup 1.0000x reference)
#include <cuda_runtime.h>
#include <math.h>

#define NV 20000
#define NB 4
#define NCF 64
#define VOX 64
#define MROWS (NV*NB)      // 80000
#define MAXW 1024
#define MAXE 131072

// ---------------- static device scratch (no allocations allowed) ----------------
__device__ __align__(16) float g_bufA[(size_t)MROWS * MAXW];
__device__ __align__(16) float g_bufB[(size_t)MROWS * MAXW];
__device__ __align__(16) float g_bufC[(size_t)MROWS * MAXW];
__device__ __align__(16) float g_s[NB * NCF];       // per-batch sampled voxel features
__device__ __align__(16) float g_off[NB * 256];     // per-batch encoder-1 offset
__device__ int   g_cnt[NV];
__device__ int   g_cur[NV];
__device__ int   g_rowptr[NV + 1];
__device__ float g_dinv[NV];
__device__ float g_selfw[NV];
__device__ int   g_csrc[MAXE];
__device__ float g_cw[MAXE];

// ---------------- voxel sample: constant grid point (-1/1.5 in all dims) ----------------
__global__ void k_vfeat(const float* __restrict__ feat) {
    int t = threadIdx.x;
    if (t >= NB * NCF) return;
    int b = t / NCF, c = t % NCF;
    float vn = -1.0f / 1.5f;
    float x = (vn + 1.0f) * 0.5f * (float)(VOX - 1);
    x = fminf(fmaxf(x, 0.0f), (float)(VOX - 1));
    float x0f = floorf(x);
    float w = x - x0f;
    int i0 = (int)x0f;
    if (i0 < 0) i0 = 0;
    if (i0 > VOX - 1) i0 = VOX - 1;
    int i1 = i0 + 1;
    if (i1 > VOX - 1) i1 = VOX - 1;
    const float* f = feat + (size_t)(b * NCF + c) * VOX * VOX * VOX;
    #define FV(z, y, xx) f[((z) * VOX + (y)) * VOX + (xx)]
    float c00 = FV(i0, i0, i0) * (1.0f - w) + FV(i0, i0, i1) * w;
    float c01 = FV(i0, i1, i0) * (1.0f - w) + FV(i0, i1, i1) * w;
    float c10 = FV(i1, i0, i0) * (1.0f - w) + FV(i1, i0, i1) * w;
    float c11 = FV(i1, i1, i0) * (1.0f - w) + FV(i1, i1, i1) * w;
    #undef FV
    float c0 = c00 * (1.0f - w) + c01 * w;
    float c1 = c10 * (1.0f - w) + c11 * w;
    g_s[t] = c0 * (1.0f - w) + c1 * w;
}

// off[b][j] = b1[j] + sum_c s[b][c] * W1[3+c][j]
__global__ void k_off(const float* __restrict__ W1, const float* __restrict__ b1) {
    int b = blockIdx.x;
    int j = threadIdx.x;
    float acc = b1[j];
    #pragma unroll 8
    for (int c = 0; c < NCF; c++)
        acc += g_s[b * NCF + c] * W1[(3 + c) * 256 + j];
    g_off[b * 256 + j] = acc;
}

// encoder layer 1: bufA[row(n,b)][j] = relu(v.W1[:3] + off[b])
__global__ void k_enc1(const float* __restrict__ V, const float* __restrict__ W1) {
    int row = blockIdx.x;          // 0..MROWS-1
    int j = threadIdx.x;           // 0..255
    int n = row >> 2, b = row & 3;
    float vx = V[n * 3 + 0], vy = V[n * 3 + 1], vz = V[n * 3 + 2];
    float acc = g_off[b * 256 + j] + vx * W1[j] + vy * W1[256 + j] + vz * W1[512 + j];
    g_bufA[(size_t)row * 256 + j] = fmaxf(acc, 0.0f);
}

// ---------------- graph preprocessing ----------------
__global__ void k_zero() {
    int i = blockIdx.x * 256 + threadIdx.x;
    if (i < NV) { g_cnt[i] = 0; g_cur[i] = 0; }
}
__global__ void k_count(const int* __restrict__ dst, int E) {
    int e = blockIdx.x * 256 + threadIdx.x;
    if (e < E) atomicAdd(&g_cnt[dst[e]], 1);
}
__global__ void k_scan() {   // single block, 1024 threads
    __shared__ int part[1024];
    int t = threadIdx.x;
    const int SEG = 20;      // 1024*20 >= NV
    int base = t * SEG;
    int s = 0;
    for (int i = 0; i < SEG; i++) {
        int idx = base + i;
        if (idx < NV) s += g_cnt[idx];
    }
    part[t] = s;
    __syncthreads();
    for (int off = 1; off < 1024; off <<= 1) {
        int v = (t >= off) ? part[t - off] : 0;
        __syncthreads();
        part[t] += v;
        __syncthreads();
    }
    int run = (t == 0) ? 0 : part[t - 1];
    for (int i = 0; i < SEG; i++) {
        int idx = base + i;
        if (idx < NV) { g_rowptr[idx] = run; run += g_cnt[idx]; }
    }
    if (t == 1023) g_rowptr[NV] = part[1023];
}
__global__ void k_dinv() {
    int n = blockIdx.x * 256 + threadIdx.x;
    if (n < NV) {
        float d = (float)g_cnt[n] + 1.0f;
        float di = 1.0f / sqrtf(d);
        g_dinv[n] = di;
        g_selfw[n] = di * di;
    }
}
__global__ void k_fill(const int* __restrict__ src, const int* __restrict__ dst, int E) {
    int e = blockIdx.x * 256 + threadIdx.x;
    if (e >= E) return;
    int s = src[e], d = dst[e];
    int slot = atomicAdd(&g_cur[d], 1);
    int p = g_rowptr[d] + slot;
    g_csrc[p] = s;
    g_cw[p] = g_dinv[s] * g_dinv[d];
}
__global__ void k_sort() {   // deterministic neighbor order (src unique per dst)
    int n = blockIdx.x * 256 + threadIdx.x;
    if (n >= NV) return;
    int a = g_rowptr[n], bnd = g_rowptr[n + 1];
    for (int i = a + 1; i < bnd; i++) {
        int key = g_csrc[i]; float kw = g_cw[i];
        int j = i - 1;
        while (j >= a && g_csrc[j] > key) {
            g_csrc[j + 1] = g_csrc[j]; g_cw[j + 1] = g_cw[j]; j--;
        }
        g_csrc[j + 1] = key; g_cw[j + 1] = kw;
    }
}

// ---------------- fp32 SGEMM: C[M,N] = A[M,K] @ W[K,N] (+bias, relu) ----------------
// 128x128 tile, BK=8, 256 threads, 8x8 per thread. M divisible by 128, K by 8, N by 4.
__global__ __launch_bounds__(256) void k_gemm(const float* __restrict__ A,
                                              const float* __restrict__ W,
                                              float* __restrict__ C,
                                              int K, int N,
                                              const float* __restrict__ bias, int fuse) {
    __shared__ float As[8][128];
    __shared__ float Bs[8][128];
    int tid = threadIdx.x;
    int bm = blockIdx.y * 128;
    int bn = blockIdx.x * 128;
    int tx = tid & 15, ty = tid >> 4;

    int arow = tid >> 1;
    int akk = (tid & 1) * 4;
    int bk = tid >> 5;
    int bcol = (tid & 31) * 4;

    float acc[8][8];
    #pragma unroll
    for (int i = 0; i < 8; i++)
        #pragma unroll
        for (int j = 0; j < 8; j++) acc[i][j] = 0.0f;

    for (int k0 = 0; k0 < K; k0 += 8) {
        float4 av = *reinterpret_cast<const float4*>(A + (size_t)(bm + arow) * K + k0 + akk);
        As[akk + 0][arow] = av.x;
        As[akk + 1][arow] = av.y;
        As[akk + 2][arow] = av.z;
        As[akk + 3][arow] = av.w;
        float4 bv = make_float4(0.f, 0.f, 0.f, 0.f);
        if (bn + bcol < N)
            bv = *reinterpret_cast<const float4*>(W + (size_t)(k0 + bk) * N + bn + bcol);
        Bs[bk][bcol + 0] = bv.x;
        Bs[bk][bcol + 1] = bv.y;
        Bs[bk][bcol + 2] = bv.z;
        Bs[bk][bcol + 3] = bv.w;
        __syncthreads();
        #pragma unroll
        for (int k = 0; k < 8; k++) {
            float a[8], b[8];
            #pragma unroll
            for (int i = 0; i < 8; i++) a[i] = As[k][ty * 8 + i];
            #pragma unroll
            for (int j = 0; j < 8; j++) b[j] = Bs[k][tx * 8 + j];
            #pragma unroll
            for (int i = 0; i < 8; i++)
                #pragma unroll
                for (int j = 0; j < 8; j++) acc[i][j] += a[i] * b[j];
        }
        __syncthreads();
    }
    #pragma unroll
    for (int i = 0; i < 8; i++) {
        int m = bm + ty * 8 + i;
        #pragma unroll
        for (int j = 0; j < 8; j++) {
            int col = bn + tx * 8 + j;
            if (col < N) {
                float v = acc[i][j];
                if (fuse) v = fmaxf(v + bias[col], 0.0f);
                C[(size_t)m * N + col] = v;
            }
        }
    }
}

// ---------------- GCN combine: X = relu(selfw*H + bias + sum_nbr w*H[src]) ----------------
// rows ordered (n,b): node n occupies 4*Cout contiguous floats = Cout float4s.
__global__ void k_combine(const float* __restrict__ H, float* __restrict__ X,
                          const float* __restrict__ bias, int Cout) {
    int n = blockIdx.y;
    int i = blockIdx.x * blockDim.x + threadIdx.x;   // float4 index in [0, Cout)
    if (i >= Cout) return;
    const float4* H4 = reinterpret_cast<const float4*>(H);
    float4* X4 = reinterpret_cast<float4*>(X);
    int b = (4 * i) / Cout;
    int cbase = 4 * i - b * Cout;
    float4 bias4 = *reinterpret_cast<const float4*>(bias + cbase);
    float sw = g_selfw[n];
    size_t base = (size_t)n * Cout;
    float4 h = H4[base + i];
    float4 acc;
    acc.x = h.x * sw + bias4.x;
    acc.y = h.y * sw + bias4.y;
    acc.z = h.z * sw + bias4.z;
    acc.w = h.w * sw + bias4.w;
    int e0 = g_rowptr[n], e1 = g_rowptr[n + 1];
    for (int e = e0; e < e1; e++) {
        int s = g_csrc[e];
        float w = g_cw[e];
        float4 hs = H4[(size_t)s * Cout + i];
        acc.x += hs.x * w;
        acc.y += hs.y * w;
        acc.z += hs.z * w;
        acc.w += hs.w * w;
    }
    acc.x = fmaxf(acc.x, 0.0f);
    acc.y = fmaxf(acc.y, 0.0f);
    acc.z = fmaxf(acc.z, 0.0f);
    acc.w = fmaxf(acc.w, 0.0f);
    X4[base + i] = acc;
}

// ---------------- head layer 3: tanh, nan->0, clip, + vertices ----------------
__global__ void k_head3(const float* __restrict__ D, const float* __restrict__ W3,
                        const float* __restrict__ b3, const float* __restrict__ V,
                        float* __restrict__ out) {
    int r = blockIdx.x * blockDim.x + threadIdx.x;
    if (r >= MROWS) return;
    int n = r >> 2, b = r & 3;
    const float* d = D + (size_t)r * 64;
    float y0 = b3[0], y1 = b3[1], y2 = b3[2];
    #pragma unroll 8
    for (int c = 0; c < 64; c++) {
        float v = d[c];
        y0 += v * W3[c * 3 + 0];
        y1 += v * W3[c * 3 + 1];
        y2 += v * W3[c * 3 + 2];
    }
    float ys[3] = {y0, y1, y2};
    #pragma unroll
    for (int k = 0; k < 3; k++) {
        float y = tanhf(ys[k]);
        if (isnan(y)) y = 0.0f;
        y = fminf(fmaxf(y, -2.5f), 2.5f);
        out[((size_t)b * NV + n) * 3 + k] = V[n * 3 + k] + y;
    }
}

// ---------------- host driver ----------------
extern "C" void kernel_launch(void* const* d_in, const int* in_sizes, int n_in,
                              void* d_out, int out_size) {
    const float* feat  = (const float*)d_in[0];
    const float* verts = (const float*)d_in[1];
    const int*   eidx  = (const int*)d_in[2];
    int E = in_sizes[2] / 2;
    if (E > MAXE) E = MAXE;
    const int* esrc = eidx;
    const int* edst = eidx + E;
    const float* encW1 = (const float*)d_in[3];
    const float* encb1 = (const float*)d_in[4];
    const float* encW2 = (const float*)d_in[5];
    const float* encb2 = (const float*)d_in[6];
    const float* gW[6] = {(const float*)d_in[7],  (const float*)d_in[9],
                          (const float*)d_in[11], (const float*)d_in[13],
                          (const float*)d_in[15], (const float*)d_in[17]};
    const float* gb[6] = {(const float*)d_in[8],  (const float*)d_in[10],
                          (const float*)d_in[12], (const float*)d_in[14],
                          (const float*)d_in[16], (const float*)d_in[18]};
    const float* hW1 = (const float*)d_in[19];
    const float* hb1 = (const float*)d_in[20];
    const float* hW2 = (const float*)d_in[21];
    const float* hb2 = (const float*)d_in[22];
    const float* hW3 = (const float*)d_in[23];
    const float* hb3 = (const float*)d_in[24];

    float *bufA, *bufB, *bufC;
    cudaGetSymbolAddress((void**)&bufA, g_bufA);
    cudaGetSymbolAddress((void**)&bufB, g_bufB);
    cudaGetSymbolAddress((void**)&bufC, g_bufC);

    // graph precompute (CSR over dst)
    k_zero<<<(NV + 255) / 256, 256>>>();
    k_count<<<(E + 255) / 256, 256>>>(edst, E);
    k_scan<<<1, 1024>>>();
    k_dinv<<<(NV + 255) / 256, 256>>>();
    k_fill<<<(E + 255) / 256, 256>>>(esrc, edst, E);
    k_sort<<<(NV + 255) / 256, 256>>>();

    // encoder
    k_vfeat<<<1, 256>>>(feat);
    k_off<<<NB, 256>>>(encW1, encb1);
    k_enc1<<<MROWS, 256>>>(verts, encW1);
    // enc layer 2: bufB = relu(bufA[80000,256] @ encW2[256,128] + b2)
    k_gemm<<<dim3(1, MROWS / 128), 256>>>(bufA, encW2, bufB, 256, 128, encb2, 1);

    // GCN stack
    const int dims[7] = {128, 256, 512, 1024, 512, 256, 128};
    float* X = bufB;
    float* other = bufA;
    for (int l = 0; l < 6; l++) {
        int Cin = dims[l], Cout = dims[l + 1];
        k_gemm<<<dim3((Cout + 127) / 128, MROWS / 128), 256>>>(X, gW[l], bufC, Cin, Cout,
                                                               (const float*)0, 0);
        k_combine<<<dim3((Cout + 127) / 128, NV), 128>>>(bufC, other, gb[l], Cout);
        float* t = X; X = other; other = t;
    }
    // head: X (== bufB) -> bufA -> bufC -> out
    k_gemm<<<dim3(1, MROWS / 128), 256>>>(X, hW1, bufA, 128, 128, hb1, 1);
    k_gemm<<<dim3(1, MROWS / 128), 256>>>(bufA, hW2, bufC, 128, 64, hb2, 1);
    k_head3<<<(MROWS + 255) / 256, 256>>>(bufC, hW3, hb3, verts, (float*)d_out);
}

// round 4
// speedup vs baseline: 1.0003x; 1.0003x over previous
#include <cuda_runtime.h>
#include <math.h>

#define NV 20000
#define NB 4
#define NCF 64
#define VOX 64
#define MROWS (NV*NB)      // 80000
#define MAXW 1024
#define MAXE 131072

// ---------------- static device scratch ----------------
__device__ __align__(16) float g_bufA[(size_t)MROWS * MAXW];
__device__ __align__(16) float g_bufB[(size_t)MROWS * MAXW];
__device__ __align__(16) float g_bufC[(size_t)MROWS * MAXW];
__device__ __align__(16) float g_s[NB * NCF];
__device__ __align__(16) float g_off[NB * 256];
__device__ int   g_cnt[NV];
__device__ int   g_cur[NV];
__device__ int   g_rowptr[NV + 1];
__device__ float g_dinv[NV];
__device__ float g_selfw[NV];
__device__ int   g_csrc[MAXE];
__device__ float g_cw[MAXE];

// ---------------- tiny kernels ----------------
__global__ void k_vfeat(const float* __restrict__ feat) {
    int t = threadIdx.x;
    if (t >= NB * NCF) return;
    int b = t / NCF, c = t % NCF;
    float vn = -1.0f / 1.5f;
    float x = (vn + 1.0f) * 0.5f * (float)(VOX - 1);
    x = fminf(fmaxf(x, 0.0f), (float)(VOX - 1));
    float x0f = floorf(x);
    float w = x - x0f;
    int i0 = (int)x0f;
    if (i0 < 0) i0 = 0;
    if (i0 > VOX - 1) i0 = VOX - 1;
    int i1 = i0 + 1;
    if (i1 > VOX - 1) i1 = VOX - 1;
    const float* f = feat + (size_t)(b * NCF + c) * VOX * VOX * VOX;
    #define FV(z, y, xx) f[((z) * VOX + (y)) * VOX + (xx)]
    float c00 = FV(i0, i0, i0) * (1.0f - w) + FV(i0, i0, i1) * w;
    float c01 = FV(i0, i1, i0) * (1.0f - w) + FV(i0, i1, i1) * w;
    float c10 = FV(i1, i0, i0) * (1.0f - w) + FV(i1, i0, i1) * w;
    float c11 = FV(i1, i1, i0) * (1.0f - w) + FV(i1, i1, i1) * w;
    #undef FV
    float c0 = c00 * (1.0f - w) + c01 * w;
    float c1 = c10 * (1.0f - w) + c11 * w;
    g_s[t] = c0 * (1.0f - w) + c1 * w;
}

__global__ void k_off(const float* __restrict__ W1, const float* __restrict__ b1) {
    int b = blockIdx.x;
    int j = threadIdx.x;
    float acc = b1[j];
    #pragma unroll 8
    for (int c = 0; c < NCF; c++)
        acc += g_s[b * NCF + c] * W1[(3 + c) * 256 + j];
    g_off[b * 256 + j] = acc;
}

__global__ void k_enc1(const float* __restrict__ V, const float* __restrict__ W1) {
    int row = blockIdx.x;
    int j = threadIdx.x;
    int n = row >> 2, b = row & 3;
    float vx = V[n * 3 + 0], vy = V[n * 3 + 1], vz = V[n * 3 + 2];
    float acc = g_off[b * 256 + j] + vx * W1[j] + vy * W1[256 + j] + vz * W1[512 + j];
    g_bufA[(size_t)row * 256 + j] = fmaxf(acc, 0.0f);
}

// ---------------- graph preprocessing ----------------
__global__ void k_zero() {
    int i = blockIdx.x * 256 + threadIdx.x;
    if (i < NV) { g_cnt[i] = 0; g_cur[i] = 0; }
}
__global__ void k_count(const int* __restrict__ dst, int E) {
    int e = blockIdx.x * 256 + threadIdx.x;
    if (e < E) atomicAdd(&g_cnt[dst[e]], 1);
}
__global__ void k_scan() {
    __shared__ int part[1024];
    int t = threadIdx.x;
    const int SEG = 20;
    int base = t * SEG;
    int s = 0;
    for (int i = 0; i < SEG; i++) {
        int idx = base + i;
        if (idx < NV) s += g_cnt[idx];
    }
    part[t] = s;
    __syncthreads();
    for (int off = 1; off < 1024; off <<= 1) {
        int v = (t >= off) ? part[t - off] : 0;
        __syncthreads();
        part[t] += v;
        __syncthreads();
    }
    int run = (t == 0) ? 0 : part[t - 1];
    for (int i = 0; i < SEG; i++) {
        int idx = base + i;
        if (idx < NV) { g_rowptr[idx] = run; run += g_cnt[idx]; }
    }
    if (t == 1023) g_rowptr[NV] = part[1023];
}
__global__ void k_dinv() {
    int n = blockIdx.x * 256 + threadIdx.x;
    if (n < NV) {
        float d = (float)g_cnt[n] + 1.0f;
        float di = 1.0f / sqrtf(d);
        g_dinv[n] = di;
        g_selfw[n] = di * di;
    }
}
__global__ void k_fill(const int* __restrict__ src, const int* __restrict__ dst, int E) {
    int e = blockIdx.x * 256 + threadIdx.x;
    if (e >= E) return;
    int s = src[e], d = dst[e];
    int slot = atomicAdd(&g_cur[d], 1);
    int p = g_rowptr[d] + slot;
    g_csrc[p] = s;
    g_cw[p] = g_dinv[s] * g_dinv[d];
}
__global__ void k_sort() {
    int n = blockIdx.x * 256 + threadIdx.x;
    if (n >= NV) return;
    int a = g_rowptr[n], bnd = g_rowptr[n + 1];
    for (int i = a + 1; i < bnd; i++) {
        int key = g_csrc[i]; float kw = g_cw[i];
        int j = i - 1;
        while (j >= a && g_csrc[j] > key) {
            g_csrc[j + 1] = g_csrc[j]; g_cw[j + 1] = g_cw[j]; j--;
        }
        g_csrc[j + 1] = key; g_cw[j + 1] = kw;
    }
}

// ---------------- 3xTF32 tensor-core GEMM ----------------
// C[M,N] = A[M,K] @ W[K,N] (+bias,relu if fuse). M % 128 == 0, K % 16 == 0, N % 64 == 0 or >=64.
__device__ __forceinline__ float cvt_tf32(float x) {
    float r;
    asm("cvt.rna.tf32.f32 %0, %1;" : "=f"(r) : "f"(x));
    return r;
}

#define MMA_TF32(C0, C1, C2, C3, A0, A1, A2, A3, B0, B1)                              \
    asm volatile("mma.sync.aligned.m16n8k8.row.col.f32.tf32.tf32.f32 "                \
                 "{%0,%1,%2,%3}, {%4,%5,%6,%7}, {%8,%9}, {%0,%1,%2,%3};\n"            \
                 : "+f"(C0), "+f"(C1), "+f"(C2), "+f"(C3)                             \
                 : "r"(__float_as_uint(A0)), "r"(__float_as_uint(A1)),                \
                   "r"(__float_as_uint(A2)), "r"(__float_as_uint(A3)),                \
                   "r"(__float_as_uint(B0)), "r"(__float_as_uint(B1)))

#define BM 128
#define BN 128
#define BKT 16
#define SPAD 2

__global__ __launch_bounds__(256) void k_gemm(const float* __restrict__ A,
                                              const float* __restrict__ W,
                                              float* __restrict__ C,
                                              int K, int N,
                                              const float* __restrict__ bias, int fuse) {
    __shared__ float2 As[BKT][BM + SPAD];
    __shared__ float2 Bs[BKT][BN + SPAD];

    int tid = threadIdx.x;
    int bm = blockIdx.y * BM;
    int bn = blockIdx.x * BN;
    int warp = tid >> 5;
    int lane = tid & 31;
    int gid = lane >> 2;      // 0..7
    int ctid = lane & 3;      // 0..3
    int wm = warp & 1;        // 0..1  -> 64-row slab
    int wn = warp >> 1;       // 0..3  -> 32-col slab

    // accumulators: 4 m-tiles x 4 n-tiles x 4 frags
    float acc[4][4][4];
    #pragma unroll
    for (int i = 0; i < 4; i++)
        #pragma unroll
        for (int j = 0; j < 4; j++)
            #pragma unroll
            for (int f = 0; f < 4; f++) acc[i][j][f] = 0.0f;

    // global-load register staging (2 float4 per matrix per thread)
    float4 areg[2], breg[2];
    // A: float4 id f = tid + i*256 : m = f>>2, kq = (f&3)*4
    // W: f = tid + i*256 : k = f>>5, c4 = (f&31)*4
    {
        #pragma unroll
        for (int i = 0; i < 2; i++) {
            int f = tid + i * 256;
            int m = f >> 2, kq = (f & 3) * 4;
            areg[i] = *reinterpret_cast<const float4*>(A + (size_t)(bm + m) * K + kq);
            int kk = f >> 5, c4 = (f & 31) * 4;
            if (bn + c4 < N)
                breg[i] = *reinterpret_cast<const float4*>(W + (size_t)kk * N + bn + c4);
            else
                breg[i] = make_float4(0.f, 0.f, 0.f, 0.f);
        }
    }

    for (int s = 0; s < K; s += BKT) {
        __syncthreads();
        // stage regs -> smem with hi/lo tf32 split
        #pragma unroll
        for (int i = 0; i < 2; i++) {
            int f = tid + i * 256;
            int m = f >> 2, kq = (f & 3) * 4;
            float v[4] = {areg[i].x, areg[i].y, areg[i].z, areg[i].w};
            #pragma unroll
            for (int j = 0; j < 4; j++) {
                float hi = cvt_tf32(v[j]);
                float lo = cvt_tf32(v[j] - hi);
                As[kq + j][m] = make_float2(hi, lo);
            }
            int kk = f >> 5, c4 = (f & 31) * 4;
            float w[4] = {breg[i].x, breg[i].y, breg[i].z, breg[i].w};
            #pragma unroll
            for (int j = 0; j < 4; j++) {
                float hi = cvt_tf32(w[j]);
                float lo = cvt_tf32(w[j] - hi);
                Bs[kk][c4 + j] = make_float2(hi, lo);
            }
        }
        __syncthreads();

        // prefetch next tile
        if (s + BKT < K) {
            #pragma unroll
            for (int i = 0; i < 2; i++) {
                int f = tid + i * 256;
                int m = f >> 2, kq = (f & 3) * 4;
                areg[i] = *reinterpret_cast<const float4*>(A + (size_t)(bm + m) * K + s + BKT + kq);
                int kk = f >> 5, c4 = (f & 31) * 4;
                if (bn + c4 < N)
                    breg[i] = *reinterpret_cast<const float4*>(W + (size_t)(s + BKT + kk) * N + bn + c4);
                else
                    breg[i] = make_float4(0.f, 0.f, 0.f, 0.f);
            }
        }

        // compute: two k8 steps
        #pragma unroll
        for (int kh = 0; kh < 2; kh++) {
            int k0 = kh * 8;
            float2 af[4][4];
            #pragma unroll
            for (int mi = 0; mi < 4; mi++) {
                int r0 = wm * 64 + mi * 16 + gid;
                af[mi][0] = As[k0 + ctid][r0];
                af[mi][1] = As[k0 + ctid][r0 + 8];
                af[mi][2] = As[k0 + ctid + 4][r0];
                af[mi][3] = As[k0 + ctid + 4][r0 + 8];
            }
            float2 bf[4][2];
            #pragma unroll
            for (int ni = 0; ni < 4; ni++) {
                int c = wn * 32 + ni * 8 + gid;
                bf[ni][0] = Bs[k0 + ctid][c];
                bf[ni][1] = Bs[k0 + ctid + 4][c];
            }
            #pragma unroll
            for (int mi = 0; mi < 4; mi++) {
                #pragma unroll
                for (int ni = 0; ni < 4; ni++) {
                    float* c4 = acc[mi][ni];
                    // hi*hi
                    MMA_TF32(c4[0], c4[1], c4[2], c4[3],
                             af[mi][0].x, af[mi][1].x, af[mi][2].x, af[mi][3].x,
                             bf[ni][0].x, bf[ni][1].x);
                    // hi*lo
                    MMA_TF32(c4[0], c4[1], c4[2], c4[3],
                             af[mi][0].x, af[mi][1].x, af[mi][2].x, af[mi][3].x,
                             bf[ni][0].y, bf[ni][1].y);
                    // lo*hi
                    MMA_TF32(c4[0], c4[1], c4[2], c4[3],
                             af[mi][0].y, af[mi][1].y, af[mi][2].y, af[mi][3].y,
                             bf[ni][0].x, bf[ni][1].x);
                }
            }
        }
    }

    // epilogue
    #pragma unroll
    for (int mi = 0; mi < 4; mi++) {
        int gm0 = bm + wm * 64 + mi * 16 + gid;
        #pragma unroll
        for (int ni = 0; ni < 4; ni++) {
            int gc = bn + wn * 32 + ni * 8 + 2 * ctid;
            if (gc < N) {
                float bx = 0.f, by = 0.f;
                if (fuse) { bx = bias[gc]; by = bias[gc + 1]; }
                float v0 = acc[mi][ni][0] + bx, v1 = acc[mi][ni][1] + by;
                float v2 = acc[mi][ni][2] + bx, v3 = acc[mi][ni][3] + by;
                if (fuse) {
                    v0 = fmaxf(v0, 0.f); v1 = fmaxf(v1, 0.f);
                    v2 = fmaxf(v2, 0.f); v3 = fmaxf(v3, 0.f);
                }
                *reinterpret_cast<float2*>(C + (size_t)gm0 * N + gc) = make_float2(v0, v1);
                *reinterpret_cast<float2*>(C + (size_t)(gm0 + 8) * N + gc) = make_float2(v2, v3);
            }
        }
    }
}

// ---------------- GCN combine ----------------
__global__ void k_combine(const float* __restrict__ H, float* __restrict__ X,
                          const float* __restrict__ bias, int Cout) {
    int n = blockIdx.y;
    int i = blockIdx.x * blockDim.x + threadIdx.x;
    if (i >= Cout) return;
    const float4* H4 = reinterpret_cast<const float4*>(H);
    float4* X4 = reinterpret_cast<float4*>(X);
    int b = (4 * i) / Cout;
    int cbase = 4 * i - b * Cout;
    float4 bias4 = *reinterpret_cast<const float4*>(bias + cbase);
    float sw = g_selfw[n];
    size_t base = (size_t)n * Cout;
    float4 h = H4[base + i];
    float4 acc;
    acc.x = h.x * sw + bias4.x;
    acc.y = h.y * sw + bias4.y;
    acc.z = h.z * sw + bias4.z;
    acc.w = h.w * sw + bias4.w;
    int e0 = g_rowptr[n], e1 = g_rowptr[n + 1];
    for (int e = e0; e < e1; e++) {
        int s = g_csrc[e];
        float w = g_cw[e];
        float4 hs = H4[(size_t)s * Cout + i];
        acc.x += hs.x * w;
        acc.y += hs.y * w;
        acc.z += hs.z * w;
        acc.w += hs.w * w;
    }
    acc.x = fmaxf(acc.x, 0.0f);
    acc.y = fmaxf(acc.y, 0.0f);
    acc.z = fmaxf(acc.z, 0.0f);
    acc.w = fmaxf(acc.w, 0.0f);
    X4[base + i] = acc;
}

// ---------------- head layer 3 ----------------
__global__ void k_head3(const float* __restrict__ D, const float* __restrict__ W3,
                        const float* __restrict__ b3, const float* __restrict__ V,
                        float* __restrict__ out) {
    int r = blockIdx.x * blockDim.x + threadIdx.x;
    if (r >= MROWS) return;
    int n = r >> 2, b = r & 3;
    const float* d = D + (size_t)r * 64;
    float y0 = b3[0], y1 = b3[1], y2 = b3[2];
    #pragma unroll 8
    for (int c = 0; c < 64; c++) {
        float v = d[c];
        y0 += v * W3[c * 3 + 0];
        y1 += v * W3[c * 3 + 1];
        y2 += v * W3[c * 3 + 2];
    }
    float ys[3] = {y0, y1, y2};
    #pragma unroll
    for (int k = 0; k < 3; k++) {
        float y = tanhf(ys[k]);
        if (isnan(y)) y = 0.0f;
        y = fminf(fmaxf(y, -2.5f), 2.5f);
        out[((size_t)b * NV + n) * 3 + k] = V[n * 3 + k] + y;
    }
}

// ---------------- host driver ----------------
extern "C" void kernel_launch(void* const* d_in, const int* in_sizes, int n_in,
                              void* d_out, int out_size) {
    const float* feat  = (const float*)d_in[0];
    const float* verts = (const float*)d_in[1];
    const int*   eidx  = (const int*)d_in[2];
    int E = in_sizes[2] / 2;
    if (E > MAXE) E = MAXE;
    const int* esrc = eidx;
    const int* edst = eidx + E;
    const float* encW1 = (const float*)d_in[3];
    const float* encb1 = (const float*)d_in[4];
    const float* encW2 = (const float*)d_in[5];
    const float* encb2 = (const float*)d_in[6];
    const float* gW[6] = {(const float*)d_in[7],  (const float*)d_in[9],
                          (const float*)d_in[11], (const float*)d_in[13],
                          (const float*)d_in[15], (const float*)d_in[17]};
    const float* gb[6] = {(const float*)d_in[8],  (const float*)d_in[10],
                          (const float*)d_in[12], (const float*)d_in[14],
                          (const float*)d_in[16], (const float*)d_in[18]};
    const float* hW1 = (const float*)d_in[19];
    const float* hb1 = (const float*)d_in[20];
    const float* hW2 = (const float*)d_in[21];
    const float* hb2 = (const float*)d_in[22];
    const float* hW3 = (const float*)d_in[23];
    const float* hb3 = (const float*)d_in[24];

    float *bufA, *bufB, *bufC;
    cudaGetSymbolAddress((void**)&bufA, g_bufA);
    cudaGetSymbolAddress((void**)&bufB, g_bufB);
    cudaGetSymbolAddress((void**)&bufC, g_bufC);

    // launch order arranged so ncu's -s 5 -c 1 window (6th launch) captures a GEMM
    k_vfeat<<<1, 256>>>(feat);                                   // 1
    k_off<<<NB, 256>>>(encW1, encb1);                            // 2
    k_enc1<<<MROWS, 256>>>(verts, encW1);                        // 3
    k_zero<<<(NV + 255) / 256, 256>>>();                         // 4
    k_count<<<(E + 255) / 256, 256>>>(edst, E);                  // 5
    k_gemm<<<dim3(1, MROWS / 128), 256>>>(bufA, encW2, bufB, 256, 128, encb2, 1);  // 6 (profiled)
    k_scan<<<1, 1024>>>();                                       // 7
    k_dinv<<<(NV + 255) / 256, 256>>>();                         // 8
    k_fill<<<(E + 255) / 256, 256>>>(esrc, edst, E);             // 9
    k_sort<<<(NV + 255) / 256, 256>>>();                         // 10

    const int dims[7] = {128, 256, 512, 1024, 512, 256, 128};
    float* X = bufB;
    float* other = bufA;
    for (int l = 0; l < 6; l++) {
        int Cin = dims[l], Cout = dims[l + 1];
        k_gemm<<<dim3((Cout + 127) / 128, MROWS / 128), 256>>>(X, gW[l], bufC, Cin, Cout,
                                                               (const float*)0, 0);
        k_combine<<<dim3((Cout + 127) / 128, NV), 128>>>(bufC, other, gb[l], Cout);
        float* t = X; X = other; other = t;
    }
    k_gemm<<<dim3(1, MROWS / 128), 256>>>(X, hW1, bufA, 128, 128, hb1, 1);
    k_gemm<<<dim3(1, MROWS / 128), 256>>>(bufA, hW2, bufC, 128, 64, hb2, 1);
    k_head3<<<(MROWS + 255) / 256, 256>>>(bufC, hW3, hb3, verts, (float*)d_out);
}

// round 6
// speedup vs baseline: 2.5184x; 2.5176x over previous
#include <cuda_runtime.h>
#include <cuda_bf16.h>
#include <math.h>
#include <stdint.h>

#define NV 20000
#define NB 4
#define NCF 64
#define VOX 64
#define MROWS (NV*NB)      // 80000
#define MTILES (MROWS/128) // 625
#define MAXW 1024
#define MAXE 131072
#define WT_TOTAL 1433600

// ---------------- static device scratch ----------------
__device__ __align__(16) float g_bufA[(size_t)MROWS * MAXW];
__device__ __align__(16) float g_bufB[(size_t)MROWS * MAXW];
__device__ __align__(16) float g_bufC[(size_t)MROWS * MAXW];
__device__ __align__(16) float g_off[NB * 256];
__device__ __align__(16) __nv_bfloat16 g_WThi[WT_TOTAL];
__device__ __align__(16) __nv_bfloat16 g_WTlo[WT_TOTAL];
__device__ int   g_cnt[NV];
__device__ int   g_cur[NV];
__device__ int   g_rowptr[NV + 1];
__device__ float g_dinv[NV];
__device__ float g_selfw[NV];
__device__ int   g_csrc[MAXE];
__device__ float g_cw[MAXE];

// ---------------- helpers ----------------
__device__ __forceinline__ uint32_t smem_u32(const void* p) {
    uint32_t a;
    asm("{ .reg .u64 t; cvta.to.shared.u64 t, %1; cvt.u32.u64 %0, t; }" : "=r"(a) : "l"(p));
    return a;
}
__device__ __forceinline__ uint32_t pack_bf2(float a, float b) {
    return (uint32_t)__bfloat16_as_ushort(__float2bfloat16_rn(a)) |
           ((uint32_t)__bfloat16_as_ushort(__float2bfloat16_rn(b)) << 16);
}

#define LDMX4(R0, R1, R2, R3, addr)                                              \
    asm volatile("ldmatrix.sync.aligned.m8n8.x4.shared.b16 {%0,%1,%2,%3}, [%4];" \
                 : "=r"(R0), "=r"(R1), "=r"(R2), "=r"(R3) : "r"(addr))

#define MMA_BF16(C, A0, A1, A2, A3, B0, B1)                                      \
    asm volatile("mma.sync.aligned.m16n8k16.row.col.f32.bf16.bf16.f32 "          \
                 "{%0,%1,%2,%3}, {%4,%5,%6,%7}, {%8,%9}, {%0,%1,%2,%3};"         \
                 : "+f"((C)[0]), "+f"((C)[1]), "+f"((C)[2]), "+f"((C)[3])        \
                 : "r"(A0), "r"(A1), "r"(A2), "r"(A3), "r"(B0), "r"(B1))

// ---------------- prep: constant voxel sample + encoder-1 offset ----------------
__global__ void k_prep(const float* __restrict__ feat, const float* __restrict__ W1,
                       const float* __restrict__ b1) {
    __shared__ float s[NB * NCF];
    int t = threadIdx.x;   // 1024
    if (t < NB * NCF) {
        int b = t / NCF, c = t % NCF;
        float vn = -1.0f / 1.5f;
        float x = (vn + 1.0f) * 0.5f * (float)(VOX - 1);
        x = fminf(fmaxf(x, 0.0f), (float)(VOX - 1));
        float x0f = floorf(x);
        float w = x - x0f;
        int i0 = (int)x0f;
        if (i0 < 0) i0 = 0;
        if (i0 > VOX - 1) i0 = VOX - 1;
        int i1 = i0 + 1;
        if (i1 > VOX - 1) i1 = VOX - 1;
        const float* f = feat + (size_t)(b * NCF + c) * VOX * VOX * VOX;
        #define FV(z, y, xx) f[((z) * VOX + (y)) * VOX + (xx)]
        float c00 = FV(i0, i0, i0) * (1.0f - w) + FV(i0, i0, i1) * w;
        float c01 = FV(i0, i1, i0) * (1.0f - w) + FV(i0, i1, i1) * w;
        float c10 = FV(i1, i0, i0) * (1.0f - w) + FV(i1, i0, i1) * w;
        float c11 = FV(i1, i1, i0) * (1.0f - w) + FV(i1, i1, i1) * w;
        #undef FV
        float c0 = c00 * (1.0f - w) + c01 * w;
        float c1 = c10 * (1.0f - w) + c11 * w;
        s[t] = c0 * (1.0f - w) + c1 * w;
    }
    __syncthreads();
    int b = t >> 8, j = t & 255;
    float acc = b1[j];
    #pragma unroll 8
    for (int c = 0; c < NCF; c++)
        acc += s[b * NCF + c] * W1[(3 + c) * 256 + j];
    g_off[t] = acc;
}

__global__ void k_enc1(const float* __restrict__ V, const float* __restrict__ W1) {
    int row = blockIdx.x;
    int j = threadIdx.x;
    int n = row >> 2, b = row & 3;
    float vx = V[n * 3 + 0], vy = V[n * 3 + 1], vz = V[n * 3 + 2];
    float acc = g_off[b * 256 + j] + vx * W1[j] + vy * W1[256 + j] + vz * W1[512 + j];
    g_bufA[(size_t)row * 256 + j] = fmaxf(acc, 0.0f);
}

// ---------------- weight transpose + bf16 hi/lo split ----------------
__global__ void k_wsplit(const float* __restrict__ W, int K, int N,
                         __nv_bfloat16* __restrict__ hi, __nv_bfloat16* __restrict__ lo) {
    int idx = blockIdx.x * 256 + threadIdx.x;
    if (idx >= N * K) return;
    int n = idx / K, k = idx - n * K;
    float v = W[k * N + n];
    __nv_bfloat16 h = __float2bfloat16_rn(v);
    hi[idx] = h;
    lo[idx] = __float2bfloat16_rn(v - __bfloat162float(h));
}

// ---------------- graph preprocessing ----------------
__global__ void k_zero() {
    int i = blockIdx.x * 256 + threadIdx.x;
    if (i < NV) { g_cnt[i] = 0; g_cur[i] = 0; }
}
__global__ void k_count(const int* __restrict__ dst, int E) {
    int e = blockIdx.x * 256 + threadIdx.x;
    if (e < E) atomicAdd(&g_cnt[dst[e]], 1);
}
__global__ void k_scan() {
    __shared__ int part[1024];
    int t = threadIdx.x;
    const int SEG = 20;
    int base = t * SEG;
    int s = 0;
    for (int i = 0; i < SEG; i++) {
        int idx = base + i;
        if (idx < NV) s += g_cnt[idx];
    }
    part[t] = s;
    __syncthreads();
    for (int off = 1; off < 1024; off <<= 1) {
        int v = (t >= off) ? part[t - off] : 0;
        __syncthreads();
        part[t] += v;
        __syncthreads();
    }
    int run = (t == 0) ? 0 : part[t - 1];
    for (int i = 0; i < SEG; i++) {
        int idx = base + i;
        if (idx < NV) { g_rowptr[idx] = run; run += g_cnt[idx]; }
    }
    if (t == 1023) g_rowptr[NV] = part[1023];
}
__global__ void k_dinv() {
    int n = blockIdx.x * 256 + threadIdx.x;
    if (n < NV) {
        float d = (float)g_cnt[n] + 1.0f;
        float di = 1.0f / sqrtf(d);
        g_dinv[n] = di;
        g_selfw[n] = di * di;
    }
}
__global__ void k_fill(const int* __restrict__ src, const int* __restrict__ dst, int E) {
    int e = blockIdx.x * 256 + threadIdx.x;
    if (e >= E) return;
    int s = src[e], d = dst[e];
    int slot = atomicAdd(&g_cur[d], 1);
    int p = g_rowptr[d] + slot;
    g_csrc[p] = s;
    g_cw[p] = g_dinv[s] * g_dinv[d];
}
__global__ void k_sort() {
    int n = blockIdx.x * 256 + threadIdx.x;
    if (n >= NV) return;
    int a = g_rowptr[n], bnd = g_rowptr[n + 1];
    for (int i = a + 1; i < bnd; i++) {
        int key = g_csrc[i]; float kw = g_cw[i];
        int j = i - 1;
        while (j >= a && g_csrc[j] > key) {
            g_csrc[j + 1] = g_csrc[j]; g_cw[j + 1] = g_cw[j]; j--;
        }
        g_csrc[j + 1] = key; g_cw[j + 1] = kw;
    }
}

// ---------------- bf16x3 mma GEMM: C[M,N] = A[M,K] @ W[K,N] ----------------
// A fp32 [M,K]; WThi/WTlo bf16 [N,K]. M%128==0, K%64==0.
// BM=128, BN=128, BK=64; 256 thr, warp tile 64x32; 144B smem row stride (conflict-free ldmatrix).
#define RSTRIDE 144
#define AHI_OFF 0
#define ALO_OFF 18432
#define BHI_OFF 36864
#define BLO_OFF 55296
#define STAGEB  73728
#define GEMM_SMEM (2 * STAGEB)

__global__ __launch_bounds__(256)
void k_mma_gemm(const float* __restrict__ A, const __nv_bfloat16* __restrict__ WThi,
                const __nv_bfloat16* __restrict__ WTlo, float* __restrict__ C,
                int K, int N, const float* __restrict__ bias, int relu) {
    extern __shared__ char smem[];
    uint32_t sb = smem_u32(smem);
    int tid = threadIdx.x;
    int warp = tid >> 5, lane = tid & 31;
    int gid = lane >> 2, ctid = lane & 3;
    int wm = warp & 1;       // 64-row slab
    int wn = warp >> 1;      // 32-col slab
    int bm = blockIdx.y * 128;
    int bn = blockIdx.x * 128;

    // lane offsets for ldmatrix
    int aLr = (lane & 7) + ((lane >> 3) & 1) * 8;
    int aLk = (lane >> 4) * 16;
    int aBase = (wm * 64 + aLr) * RSTRIDE + aLk;
    int bLr = (lane & 7) + (lane >> 4) * 8;
    int bLk = ((lane >> 3) & 1) * 16;
    int bBase = (wn * 32 + bLr) * RSTRIDE + bLk;

    float acc[4][4][4];
    #pragma unroll
    for (int i = 0; i < 4; i++)
        #pragma unroll
        for (int j = 0; j < 4; j++)
            #pragma unroll
            for (int f = 0; f < 4; f++) acc[i][j][f] = 0.0f;

    float4 aP[8], bhP[4], blP[4];
    // prefetch t=0
    #pragma unroll
    for (int i = 0; i < 8; i++) {
        int f = tid + (i << 8);
        int row = f >> 4, kc = f & 15;
        aP[i] = *reinterpret_cast<const float4*>(A + (size_t)(bm + row) * K + kc * 4);
    }
    #pragma unroll
    for (int i = 0; i < 4; i++) {
        int f = tid + (i << 8);
        int row = f >> 3, kc = f & 7;
        if (bn + row < N) {
            bhP[i] = *reinterpret_cast<const float4*>((const char*)(WThi + (size_t)(bn + row) * K) + kc * 16);
            blP[i] = *reinterpret_cast<const float4*>((const char*)(WTlo + (size_t)(bn + row) * K) + kc * 16);
        } else {
            bhP[i] = make_float4(0.f, 0.f, 0.f, 0.f);
            blP[i] = bhP[i];
        }
    }

    int T = K >> 6;
    for (int t = 0; t < T; t++) {
        char* base = smem + (t & 1) * STAGEB;
        uint32_t sbase = sb + (t & 1) * STAGEB;
        // stage regs -> smem (A split hi/lo)
        #pragma unroll
        for (int i = 0; i < 8; i++) {
            int f = tid + (i << 8);
            int row = f >> 4, kc = f & 15;
            float4 v = aP[i];
            float hx = __bfloat162float(__float2bfloat16_rn(v.x));
            float hy = __bfloat162float(__float2bfloat16_rn(v.y));
            float hz = __bfloat162float(__float2bfloat16_rn(v.z));
            float hw = __bfloat162float(__float2bfloat16_rn(v.w));
            uint2 hv, lv;
            hv.x = pack_bf2(v.x, v.y);
            hv.y = pack_bf2(v.z, v.w);
            lv.x = pack_bf2(v.x - hx, v.y - hy);
            lv.y = pack_bf2(v.z - hz, v.w - hw);
            int off = row * RSTRIDE + kc * 8;
            *reinterpret_cast<uint2*>(base + AHI_OFF + off) = hv;
            *reinterpret_cast<uint2*>(base + ALO_OFF + off) = lv;
        }
        #pragma unroll
        for (int i = 0; i < 4; i++) {
            int f = tid + (i << 8);
            int row = f >> 3, kc = f & 7;
            int off = row * RSTRIDE + kc * 16;
            *reinterpret_cast<float4*>(base + BHI_OFF + off) = bhP[i];
            *reinterpret_cast<float4*>(base + BLO_OFF + off) = blP[i];
        }
        __syncthreads();

        // prefetch t+1
        if (t + 1 < T) {
            int kt = (t + 1) << 6;
            #pragma unroll
            for (int i = 0; i < 8; i++) {
                int f = tid + (i << 8);
                int row = f >> 4, kc = f & 15;
                aP[i] = *reinterpret_cast<const float4*>(A + (size_t)(bm + row) * K + kt + kc * 4);
            }
            #pragma unroll
            for (int i = 0; i < 4; i++) {
                int f = tid + (i << 8);
                int row = f >> 3, kc = f & 7;
                if (bn + row < N) {
                    bhP[i] = *reinterpret_cast<const float4*>((const char*)(WThi + (size_t)(bn + row) * K + kt) + kc * 16);
                    blP[i] = *reinterpret_cast<const float4*>((const char*)(WTlo + (size_t)(bn + row) * K + kt) + kc * 16);
                } else {
                    bhP[i] = make_float4(0.f, 0.f, 0.f, 0.f);
                    blP[i] = bhP[i];
                }
            }
        }

        // compute 4 k16-steps
        #pragma unroll
        for (int ks = 0; ks < 4; ks++) {
            int k2 = ks * 32;   // byte offset within row
            uint32_t bh[4][2], bl[4][2];
            #pragma unroll
            for (int p = 0; p < 2; p++) {
                LDMX4(bh[2 * p][0], bh[2 * p][1], bh[2 * p + 1][0], bh[2 * p + 1][1],
                      sbase + BHI_OFF + bBase + p * (16 * RSTRIDE) + k2);
                LDMX4(bl[2 * p][0], bl[2 * p][1], bl[2 * p + 1][0], bl[2 * p + 1][1],
                      sbase + BLO_OFF + bBase + p * (16 * RSTRIDE) + k2);
            }
            #pragma unroll
            for (int mi = 0; mi < 4; mi++) {
                uint32_t ah[4], al[4];
                LDMX4(ah[0], ah[1], ah[2], ah[3],
                      sbase + AHI_OFF + aBase + mi * (16 * RSTRIDE) + k2);
                LDMX4(al[0], al[1], al[2], al[3],
                      sbase + ALO_OFF + aBase + mi * (16 * RSTRIDE) + k2);
                #pragma unroll
                for (int ni = 0; ni < 4; ni++) {
                    MMA_BF16(acc[mi][ni], ah[0], ah[1], ah[2], ah[3], bh[ni][0], bh[ni][1]);
                    MMA_BF16(acc[mi][ni], ah[0], ah[1], ah[2], ah[3], bl[ni][0], bl[ni][1]);
                    MMA_BF16(acc[mi][ni], al[0], al[1], al[2], al[3], bh[ni][0], bh[ni][1]);
                }
            }
        }
    }

    // epilogue: direct register stores
    #pragma unroll
    for (int mi = 0; mi < 4; mi++) {
        int gm0 = bm + wm * 64 + mi * 16 + gid;
        #pragma unroll
        for (int ni = 0; ni < 4; ni++) {
            int gc = bn + wn * 32 + ni * 8 + 2 * ctid;
            if (gc < N) {
                float bx = 0.f, by = 0.f;
                if (bias) { bx = bias[gc]; by = bias[gc + 1]; }
                float v0 = acc[mi][ni][0] + bx, v1 = acc[mi][ni][1] + by;
                float v2 = acc[mi][ni][2] + bx, v3 = acc[mi][ni][3] + by;
                if (relu) {
                    v0 = fmaxf(v0, 0.f); v1 = fmaxf(v1, 0.f);
                    v2 = fmaxf(v2, 0.f); v3 = fmaxf(v3, 0.f);
                }
                *reinterpret_cast<float2*>(C + (size_t)gm0 * N + gc) = make_float2(v0, v1);
                *reinterpret_cast<float2*>(C + (size_t)(gm0 + 8) * N + gc) = make_float2(v2, v3);
            }
        }
    }
}

// ---------------- GCN aggregate: X = [relu]( selfw*H + [bias] + sum w*H[src] ) ----------------
__global__ void k_agg(const float* __restrict__ H, float* __restrict__ X,
                      const float* __restrict__ bias, int C4, int relu) {
    int n = blockIdx.y;
    int i = blockIdx.x * blockDim.x + threadIdx.x;
    if (i >= C4) return;
    const float4* H4 = reinterpret_cast<const float4*>(H);
    float4* X4 = reinterpret_cast<float4*>(X);
    float4 bias4 = make_float4(0.f, 0.f, 0.f, 0.f);
    if (bias) {
        int b = (4 * i) / C4;
        int cbase = 4 * i - b * C4;
        bias4 = *reinterpret_cast<const float4*>(bias + cbase);
    }
    float sw = g_selfw[n];
    size_t base = (size_t)n * C4;
    float4 h = H4[base + i];
    float4 acc;
    acc.x = h.x * sw + bias4.x;
    acc.y = h.y * sw + bias4.y;
    acc.z = h.z * sw + bias4.z;
    acc.w = h.w * sw + bias4.w;
    int e0 = g_rowptr[n], e1 = g_rowptr[n + 1];
    for (int e = e0; e < e1; e++) {
        int s = g_csrc[e];
        float w = g_cw[e];
        float4 hs = H4[(size_t)s * C4 + i];
        acc.x += hs.x * w;
        acc.y += hs.y * w;
        acc.z += hs.z * w;
        acc.w += hs.w * w;
    }
    if (relu) {
        acc.x = fmaxf(acc.x, 0.0f);
        acc.y = fmaxf(acc.y, 0.0f);
        acc.z = fmaxf(acc.z, 0.0f);
        acc.w = fmaxf(acc.w, 0.0f);
    }
    X4[base + i] = acc;
}

// ---------------- head layer 3 ----------------
__global__ void k_head3(const float* __restrict__ D, const float* __restrict__ W3,
                        const float* __restrict__ b3, const float* __restrict__ V,
                        float* __restrict__ out) {
    int r = blockIdx.x * blockDim.x + threadIdx.x;
    if (r >= MROWS) return;
    int n = r >> 2, b = r & 3;
    const float* d = D + (size_t)r * 64;
    float y0 = b3[0], y1 = b3[1], y2 = b3[2];
    #pragma unroll 8
    for (int c = 0; c < 64; c++) {
        float v = d[c];
        y0 += v * W3[c * 3 + 0];
        y1 += v * W3[c * 3 + 1];
        y2 += v * W3[c * 3 + 2];
    }
    float ys[3] = {y0, y1, y2};
    #pragma unroll
    for (int k = 0; k < 3; k++) {
        float y = tanhf(ys[k]);
        if (isnan(y)) y = 0.0f;
        y = fminf(fmaxf(y, -2.5f), 2.5f);
        out[((size_t)b * NV + n) * 3 + k] = V[n * 3 + k] + y;
    }
}

// ---------------- host driver ----------------
extern "C" void kernel_launch(void* const* d_in, const int* in_sizes, int n_in,
                              void* d_out, int out_size) {
    const float* feat  = (const float*)d_in[0];
    const float* verts = (const float*)d_in[1];
    const int*   eidx  = (const int*)d_in[2];
    int E = in_sizes[2] / 2;
    if (E > MAXE) E = MAXE;
    const int* esrc = eidx;
    const int* edst = eidx + E;
    const float* encW1 = (const float*)d_in[3];
    const float* encb1 = (const float*)d_in[4];
    const float* encW2 = (const float*)d_in[5];
    const float* encb2 = (const float*)d_in[6];
    const float* gW[6] = {(const float*)d_in[7],  (const float*)d_in[9],
                          (const float*)d_in[11], (const float*)d_in[13],
                          (const float*)d_in[15], (const float*)d_in[17]};
    const float* gb[6] = {(const float*)d_in[8],  (const float*)d_in[10],
                          (const float*)d_in[12], (const float*)d_in[14],
                          (const float*)d_in[16], (const float*)d_in[18]};
    const float* hW1 = (const float*)d_in[19];
    const float* hb1 = (const float*)d_in[20];
    const float* hW2 = (const float*)d_in[21];
    const float* hb2 = (const float*)d_in[22];
    const float* hW3 = (const float*)d_in[23];
    const float* hb3 = (const float*)d_in[24];

    float *bufA, *bufB, *bufC;
    __nv_bfloat16 *wthi, *wtlo;
    cudaGetSymbolAddress((void**)&bufA, g_bufA);
    cudaGetSymbolAddress((void**)&bufB, g_bufB);
    cudaGetSymbolAddress((void**)&bufC, g_bufC);
    cudaGetSymbolAddress((void**)&wthi, g_WThi);
    cudaGetSymbolAddress((void**)&wtlo, g_WTlo);

    cudaFuncSetAttribute(k_mma_gemm, cudaFuncAttributeMaxDynamicSharedMemorySize, GEMM_SMEM);

    const int woff[9] = {0, 32768, 65536, 196608, 720896, 1245184, 1376256, 1409024, 1425408};
    const int wk[9]   = {256, 128, 256, 512, 1024, 512, 256, 128, 128};
    const int wn[9]   = {128, 256, 512, 1024, 512, 256, 128, 128, 64};
    const float* wptr[9] = {encW2, gW[0], gW[1], gW[2], gW[3], gW[4], gW[5], hW1, hW2};

    auto gemm = [&](const float* A, int li, float* C, const float* bias, int relu) {
        dim3 grid((wn[li] + 127) / 128, MTILES);
        k_mma_gemm<<<grid, 256, GEMM_SMEM>>>(A, wthi + woff[li], wtlo + woff[li], C,
                                             wk[li], wn[li], bias, relu);
    };

    // launch order: #4 = first big GEMM (ncu capture window)
    k_prep<<<1, 1024>>>(feat, encW1, encb1);                                  // 1
    k_wsplit<<<(wn[0] * wk[0] + 255) / 256, 256>>>(wptr[0], wk[0], wn[0],
                                                   wthi + woff[0], wtlo + woff[0]); // 2
    k_enc1<<<MROWS, 256>>>(verts, encW1);                                     // 3
    gemm(bufA, 0, bufB, encb2, 1);                                            // 4 (profiled)

    for (int li = 1; li < 9; li++)
        k_wsplit<<<(wn[li] * wk[li] + 255) / 256, 256>>>(wptr[li], wk[li], wn[li],
                                                         wthi + woff[li], wtlo + woff[li]);
    k_zero<<<(NV + 255) / 256, 256>>>();
    k_count<<<(E + 255) / 256, 256>>>(edst, E);
    k_scan<<<1, 1024>>>();
    k_dinv<<<(NV + 255) / 256, 256>>>();
    k_fill<<<(E + 255) / 256, 256>>>(esrc, edst, E);
    k_sort<<<(NV + 255) / 256, 256>>>();

    // g1..g3: aggregate-then-GEMM (Cin < Cout); bias+relu fused in GEMM
    k_agg<<<dim3(1, NV), 128>>>(bufB, bufC, (const float*)0, 128, 0);
    gemm(bufC, 1, bufA, gb[0], 1);
    k_agg<<<dim3(2, NV), 128>>>(bufA, bufC, (const float*)0, 256, 0);
    gemm(bufC, 2, bufB, gb[1], 1);
    k_agg<<<dim3(4, NV), 128>>>(bufB, bufC, (const float*)0, 512, 0);
    gemm(bufC, 3, bufA, gb[2], 1);
    // g4..g6: GEMM-then-aggregate (Cout < Cin); bias+relu fused in aggregate
    gemm(bufA, 4, bufC, (const float*)0, 0);
    k_agg<<<dim3(4, NV), 128>>>(bufC, bufB, gb[3], 512, 1);
    gemm(bufB, 5, bufC, (const float*)0, 0);
    k_agg<<<dim3(2, NV), 128>>>(bufC, bufA, gb[4], 256, 1);
    gemm(bufA, 6, bufC, (const float*)0, 0);
    k_agg<<<dim3(1, NV), 128>>>(bufC, bufB, gb[5], 128, 1);
    // head
    gemm(bufB, 7, bufA, hb1, 1);
    gemm(bufA, 8, bufC, hb2, 1);
    k_head3<<<(MROWS + 255) / 256, 256>>>(bufC, hW3, hb3, verts, (float*)d_out);
}

// round 8
// speedup vs baseline: 2.6790x; 1.0638x over previous
#include <cuda_runtime.h>
#include <cuda_bf16.h>
#include <math.h>
#include <stdint.h>

#define NV 20000
#define NB 4
#define NCF 64
#define VOX 64
#define MROWS (NV*NB)      // 80000
#define MTILES (MROWS/128) // 625
#define MAXW 1024
#define MAXE 131072
#define WT_TOTAL 1433600

// ---------------- static device scratch ----------------
__device__ __align__(16) float g_bufA[(size_t)MROWS * MAXW];
__device__ __align__(16) float g_bufB[(size_t)MROWS * MAXW];
__device__ __align__(16) float g_bufC[(size_t)MROWS * MAXW];
__device__ __align__(16) float g_off[NB * 256];
__device__ __align__(16) __nv_bfloat16 g_WThi[WT_TOTAL];
__device__ __align__(16) __nv_bfloat16 g_WTlo[WT_TOTAL];
__device__ int   g_cnt[NV];
__device__ int   g_cur[NV];
__device__ int   g_rowptr[NV + 1];
__device__ float g_dinv[NV];
__device__ float g_selfw[NV];
__device__ int   g_csrc[MAXE];
__device__ float g_cw[MAXE];

// ---------------- helpers ----------------
__device__ __forceinline__ uint32_t smem_u32(const void* p) {
    uint32_t a;
    asm("{ .reg .u64 t; cvta.to.shared.u64 t, %1; cvt.u32.u64 %0, t; }" : "=r"(a) : "l"(p));
    return a;
}
__device__ __forceinline__ uint32_t pack_bf2(float a, float b) {
    return (uint32_t)__bfloat16_as_ushort(__float2bfloat16_rn(a)) |
           ((uint32_t)__bfloat16_as_ushort(__float2bfloat16_rn(b)) << 16);
}

#define LDMX4(R0, R1, R2, R3, addr)                                              \
    asm volatile("ldmatrix.sync.aligned.m8n8.x4.shared.b16 {%0,%1,%2,%3}, [%4];" \
                 : "=r"(R0), "=r"(R1), "=r"(R2), "=r"(R3) : "r"(addr))

#define MMA_BF16(C, A0, A1, A2, A3, B0, B1)                                      \
    asm volatile("mma.sync.aligned.m16n8k16.row.col.f32.bf16.bf16.f32 "          \
                 "{%0,%1,%2,%3}, {%4,%5,%6,%7}, {%8,%9}, {%0,%1,%2,%3};"         \
                 : "+f"((C)[0]), "+f"((C)[1]), "+f"((C)[2]), "+f"((C)[3])        \
                 : "r"(A0), "r"(A1), "r"(A2), "r"(A3), "r"(B0), "r"(B1))

// ---------------- prep: constant voxel sample + encoder-1 offset ----------------
__global__ void k_prep(const float* __restrict__ feat, const float* __restrict__ W1,
                       const float* __restrict__ b1) {
    __shared__ float s[NB * NCF];
    int t = threadIdx.x;   // 1024
    if (t < NB * NCF) {
        int b = t / NCF, c = t % NCF;
        float vn = -1.0f / 1.5f;
        float x = (vn + 1.0f) * 0.5f * (float)(VOX - 1);
        x = fminf(fmaxf(x, 0.0f), (float)(VOX - 1));
        float x0f = floorf(x);
        float w = x - x0f;
        int i0 = (int)x0f;
        if (i0 < 0) i0 = 0;
        if (i0 > VOX - 1) i0 = VOX - 1;
        int i1 = i0 + 1;
        if (i1 > VOX - 1) i1 = VOX - 1;
        const float* f = feat + (size_t)(b * NCF + c) * VOX * VOX * VOX;
        #define FV(z, y, xx) f[((z) * VOX + (y)) * VOX + (xx)]
        float c00 = FV(i0, i0, i0) * (1.0f - w) + FV(i0, i0, i1) * w;
        float c01 = FV(i0, i1, i0) * (1.0f - w) + FV(i0, i1, i1) * w;
        float c10 = FV(i1, i0, i0) * (1.0f - w) + FV(i1, i0, i1) * w;
        float c11 = FV(i1, i1, i0) * (1.0f - w) + FV(i1, i1, i1) * w;
        #undef FV
        float c0 = c00 * (1.0f - w) + c01 * w;
        float c1 = c10 * (1.0f - w) + c11 * w;
        s[t] = c0 * (1.0f - w) + c1 * w;
    }
    __syncthreads();
    int b = t >> 8, j = t & 255;
    float acc = b1[j];
    #pragma unroll 8
    for (int c = 0; c < NCF; c++)
        acc += s[b * NCF + c] * W1[(3 + c) * 256 + j];
    g_off[t] = acc;
}

__global__ void k_enc1(const float* __restrict__ V, const float* __restrict__ W1) {
    int row = blockIdx.x;
    int j = threadIdx.x;
    int n = row >> 2, b = row & 3;
    float vx = V[n * 3 + 0], vy = V[n * 3 + 1], vz = V[n * 3 + 2];
    float acc = g_off[b * 256 + j] + vx * W1[j] + vy * W1[256 + j] + vz * W1[512 + j];
    g_bufA[(size_t)row * 256 + j] = fmaxf(acc, 0.0f);
}

// ---------------- weight transpose + bf16 hi/lo split ----------------
__global__ void k_wsplit(const float* __restrict__ W, int K, int N,
                         __nv_bfloat16* __restrict__ hi, __nv_bfloat16* __restrict__ lo) {
    int idx = blockIdx.x * 256 + threadIdx.x;
    if (idx >= N * K) return;
    int n = idx / K, k = idx - n * K;
    float v = W[k * N + n];
    __nv_bfloat16 h = __float2bfloat16_rn(v);
    hi[idx] = h;
    lo[idx] = __float2bfloat16_rn(v - __bfloat162float(h));
}

// ---------------- graph preprocessing ----------------
__global__ void k_zero() {
    int i = blockIdx.x * 256 + threadIdx.x;
    if (i < NV) { g_cnt[i] = 0; g_cur[i] = 0; }
}
__global__ void k_count(const int* __restrict__ dst, int E) {
    int e = blockIdx.x * 256 + threadIdx.x;
    if (e < E) atomicAdd(&g_cnt[dst[e]], 1);
}
__global__ void k_scan() {
    __shared__ int part[1024];
    int t = threadIdx.x;
    const int SEG = 20;
    int base = t * SEG;
    int s = 0;
    for (int i = 0; i < SEG; i++) {
        int idx = base + i;
        if (idx < NV) s += g_cnt[idx];
    }
    part[t] = s;
    __syncthreads();
    for (int off = 1; off < 1024; off <<= 1) {
        int v = (t >= off) ? part[t - off] : 0;
        __syncthreads();
        part[t] += v;
        __syncthreads();
    }
    int run = (t == 0) ? 0 : part[t - 1];
    for (int i = 0; i < SEG; i++) {
        int idx = base + i;
        if (idx < NV) { g_rowptr[idx] = run; run += g_cnt[idx]; }
    }
    if (t == 1023) g_rowptr[NV] = part[1023];
}
__global__ void k_dinv() {
    int n = blockIdx.x * 256 + threadIdx.x;
    if (n < NV) {
        float d = (float)g_cnt[n] + 1.0f;
        float di = 1.0f / sqrtf(d);
        g_dinv[n] = di;
        g_selfw[n] = di * di;
    }
}
__global__ void k_fill(const int* __restrict__ src, const int* __restrict__ dst, int E) {
    int e = blockIdx.x * 256 + threadIdx.x;
    if (e >= E) return;
    int s = src[e], d = dst[e];
    int slot = atomicAdd(&g_cur[d], 1);
    int p = g_rowptr[d] + slot;
    g_csrc[p] = s;
    g_cw[p] = g_dinv[s] * g_dinv[d];
}
__global__ void k_sort() {
    int n = blockIdx.x * 256 + threadIdx.x;
    if (n >= NV) return;
    int a = g_rowptr[n], bnd = g_rowptr[n + 1];
    for (int i = a + 1; i < bnd; i++) {
        int key = g_csrc[i]; float kw = g_cw[i];
        int j = i - 1;
        while (j >= a && g_csrc[j] > key) {
            g_csrc[j + 1] = g_csrc[j]; g_cw[j + 1] = g_cw[j]; j--;
        }
        g_csrc[j + 1] = key; g_cw[j + 1] = kw;
    }
}

// ---------------- bf16x3 mma GEMM, 512 threads: C[M,N] = A[M,K] @ W[K,N] ----------------
// A fp32 [M,K]; WThi/WTlo bf16 [N,K]. M%128==0, K%64==0.
// BM=128, BN=128, BK=64; 512 thr (16 warps), warp tile 32x32; 144B row stride.
#define RSTRIDE 144
#define AHI_OFF 0
#define ALO_OFF 18432
#define BHI_OFF 36864
#define BLO_OFF 55296
#define STAGEB  73728
#define GEMM_SMEM (2 * STAGEB)

__global__ __launch_bounds__(512, 1)
void k_mma_gemm(const float* __restrict__ A, const __nv_bfloat16* __restrict__ WThi,
                const __nv_bfloat16* __restrict__ WTlo, float* __restrict__ C,
                int K, int N, const float* __restrict__ bias, int relu) {
    extern __shared__ char smem[];
    uint32_t sb = smem_u32(smem);
    int tid = threadIdx.x;
    int warp = tid >> 5, lane = tid & 31;
    int gid = lane >> 2, ctid = lane & 3;
    int wm = warp & 3;       // 4 slabs of 32 rows
    int wn = warp >> 2;      // 4 slabs of 32 cols
    int bm = blockIdx.y * 128;
    int bn = blockIdx.x * 128;

    // ldmatrix lane addressing
    int aLr = (lane & 7) + ((lane >> 3) & 1) * 8;
    int aLk = (lane >> 4) * 16;
    int aBase = (wm * 32 + aLr) * RSTRIDE + aLk;
    int bLr = (lane & 7) + (lane >> 4) * 8;
    int bLk = ((lane >> 3) & 1) * 16;
    int bBase = (wn * 32 + bLr) * RSTRIDE + bLk;

    float acc[2][4][4];
    #pragma unroll
    for (int i = 0; i < 2; i++)
        #pragma unroll
        for (int j = 0; j < 4; j++)
            #pragma unroll
            for (int f = 0; f < 4; f++) acc[i][j][f] = 0.0f;

    float4 aP[4], bhP[2], blP[2];
    // prefetch t=0
    #pragma unroll
    for (int i = 0; i < 4; i++) {
        int f = tid + (i << 9);
        int row = f >> 4, kc = f & 15;
        aP[i] = *reinterpret_cast<const float4*>(A + (size_t)(bm + row) * K + kc * 4);
    }
    #pragma unroll
    for (int i = 0; i < 2; i++) {
        int f = tid + (i << 9);
        int row = f >> 3, kc = f & 7;
        if (bn + row < N) {
            bhP[i] = *reinterpret_cast<const float4*>((const char*)(WThi + (size_t)(bn + row) * K) + kc * 16);
            blP[i] = *reinterpret_cast<const float4*>((const char*)(WTlo + (size_t)(bn + row) * K) + kc * 16);
        } else {
            bhP[i] = make_float4(0.f, 0.f, 0.f, 0.f);
            blP[i] = bhP[i];
        }
    }

    int T = K >> 6;
    for (int t = 0; t < T; t++) {
        char* base = smem + (t & 1) * STAGEB;
        uint32_t sbase = sb + (t & 1) * STAGEB;
        // stage regs -> smem (A split hi/lo)
        #pragma unroll
        for (int i = 0; i < 4; i++) {
            int f = tid + (i << 9);
            int row = f >> 4, kc = f & 15;
            float4 v = aP[i];
            float hx = __bfloat162float(__float2bfloat16_rn(v.x));
            float hy = __bfloat162float(__float2bfloat16_rn(v.y));
            float hz = __bfloat162float(__float2bfloat16_rn(v.z));
            float hw = __bfloat162float(__float2bfloat16_rn(v.w));
            uint2 hv, lv;
            hv.x = pack_bf2(v.x, v.y);
            hv.y = pack_bf2(v.z, v.w);
            lv.x = pack_bf2(v.x - hx, v.y - hy);
            lv.y = pack_bf2(v.z - hz, v.w - hw);
            int off = row * RSTRIDE + kc * 8;
            *reinterpret_cast<uint2*>(base + AHI_OFF + off) = hv;
            *reinterpret_cast<uint2*>(base + ALO_OFF + off) = lv;
        }
        #pragma unroll
        for (int i = 0; i < 2; i++) {
            int f = tid + (i << 9);
            int row = f >> 3, kc = f & 7;
            int off = row * RSTRIDE + kc * 16;
            *reinterpret_cast<float4*>(base + BHI_OFF + off) = bhP[i];
            *reinterpret_cast<float4*>(base + BLO_OFF + off) = blP[i];
        }
        __syncthreads();

        // prefetch t+1
        if (t + 1 < T) {
            int kt = (t + 1) << 6;
            #pragma unroll
            for (int i = 0; i < 4; i++) {
                int f = tid + (i << 9);
                int row = f >> 4, kc = f & 15;
                aP[i] = *reinterpret_cast<const float4*>(A + (size_t)(bm + row) * K + kt + kc * 4);
            }
            #pragma unroll
            for (int i = 0; i < 2; i++) {
                int f = tid + (i << 9);
                int row = f >> 3, kc = f & 7;
                if (bn + row < N) {
                    bhP[i] = *reinterpret_cast<const float4*>((const char*)(WThi + (size_t)(bn + row) * K + kt) + kc * 16);
                    blP[i] = *reinterpret_cast<const float4*>((const char*)(WTlo + (size_t)(bn + row) * K + kt) + kc * 16);
                } else {
                    bhP[i] = make_float4(0.f, 0.f, 0.f, 0.f);
                    blP[i] = bhP[i];
                }
            }
        }

        // compute 4 k16-steps
        #pragma unroll
        for (int ks = 0; ks < 4; ks++) {
            int k2 = ks * 32;   // byte offset within row
            uint32_t bh[4][2], bl[4][2];
            #pragma unroll
            for (int p = 0; p < 2; p++) {
                LDMX4(bh[2 * p][0], bh[2 * p][1], bh[2 * p + 1][0], bh[2 * p + 1][1],
                      sbase + BHI_OFF + bBase + p * (16 * RSTRIDE) + k2);
                LDMX4(bl[2 * p][0], bl[2 * p][1], bl[2 * p + 1][0], bl[2 * p + 1][1],
                      sbase + BLO_OFF + bBase + p * (16 * RSTRIDE) + k2);
            }
            #pragma unroll
            for (int mi = 0; mi < 2; mi++) {
                uint32_t ah[4], al[4];
                LDMX4(ah[0], ah[1], ah[2], ah[3],
                      sbase + AHI_OFF + aBase + mi * (16 * RSTRIDE) + k2);
                LDMX4(al[0], al[1], al[2], al[3],
                      sbase + ALO_OFF + aBase + mi * (16 * RSTRIDE) + k2);
                #pragma unroll
                for (int ni = 0; ni < 4; ni++) {
                    MMA_BF16(acc[mi][ni], ah[0], ah[1], ah[2], ah[3], bh[ni][0], bh[ni][1]);
                    MMA_BF16(acc[mi][ni], ah[0], ah[1], ah[2], ah[3], bl[ni][0], bl[ni][1]);
                    MMA_BF16(acc[mi][ni], al[0], al[1], al[2], al[3], bh[ni][0], bh[ni][1]);
                }
            }
        }
    }

    // epilogue: direct register stores
    #pragma unroll
    for (int mi = 0; mi < 2; mi++) {
        int gm0 = bm + wm * 32 + mi * 16 + gid;
        #pragma unroll
        for (int ni = 0; ni < 4; ni++) {
            int gc = bn + wn * 32 + ni * 8 + 2 * ctid;
            if (gc < N) {
                float bx = 0.f, by = 0.f;
                if (bias) { bx = bias[gc]; by = bias[gc + 1]; }
                float v0 = acc[mi][ni][0] + bx, v1 = acc[mi][ni][1] + by;
                float v2 = acc[mi][ni][2] + bx, v3 = acc[mi][ni][3] + by;
                if (relu) {
                    v0 = fmaxf(v0, 0.f); v1 = fmaxf(v1, 0.f);
                    v2 = fmaxf(v2, 0.f); v3 = fmaxf(v3, 0.f);
                }
                *reinterpret_cast<float2*>(C + (size_t)gm0 * N + gc) = make_float2(v0, v1);
                *reinterpret_cast<float2*>(C + (size_t)(gm0 + 8) * N + gc) = make_float2(v2, v3);
            }
        }
    }
}

// ---------------- GCN aggregate: X = [relu]( selfw*H + [bias] + sum w*H[src] ) ----------------
__global__ void k_agg(const float* __restrict__ H, float* __restrict__ X,
                      const float* __restrict__ bias, int C4, int relu) {
    int n = blockIdx.y;
    int i = blockIdx.x * blockDim.x + threadIdx.x;
    if (i >= C4) return;
    const float4* H4 = reinterpret_cast<const float4*>(H);
    float4* X4 = reinterpret_cast<float4*>(X);
    float4 bias4 = make_float4(0.f, 0.f, 0.f, 0.f);
    if (bias) {
        int b = (4 * i) / C4;
        int cbase = 4 * i - b * C4;
        bias4 = *reinterpret_cast<const float4*>(bias + cbase);
    }
    float sw = g_selfw[n];
    size_t base = (size_t)n * C4;
    float4 h = H4[base + i];
    float4 acc;
    acc.x = h.x * sw + bias4.x;
    acc.y = h.y * sw + bias4.y;
    acc.z = h.z * sw + bias4.z;
    acc.w = h.w * sw + bias4.w;
    int e0 = g_rowptr[n], e1 = g_rowptr[n + 1];
    for (int e = e0; e < e1; e++) {
        int s = g_csrc[e];
        float w = g_cw[e];
        float4 hs = H4[(size_t)s * C4 + i];
        acc.x += hs.x * w;
        acc.y += hs.y * w;
        acc.z += hs.z * w;
        acc.w += hs.w * w;
    }
    if (relu) {
        acc.x = fmaxf(acc.x, 0.0f);
        acc.y = fmaxf(acc.y, 0.0f);
        acc.z = fmaxf(acc.z, 0.0f);
        acc.w = fmaxf(acc.w, 0.0f);
    }
    X4[base + i] = acc;
}

// ---------------- head layer 3 ----------------
__global__ void k_head3(const float* __restrict__ D, const float* __restrict__ W3,
                        const float* __restrict__ b3, const float* __restrict__ V,
                        float* __restrict__ out) {
    int r = blockIdx.x * blockDim.x + threadIdx.x;
    if (r >= MROWS) return;
    int n = r >> 2, b = r & 3;
    const float* d = D + (size_t)r * 64;
    float y0 = b3[0], y1 = b3[1], y2 = b3[2];
    #pragma unroll 8
    for (int c = 0; c < 64; c++) {
        float v = d[c];
        y0 += v * W3[c * 3 + 0];
        y1 += v * W3[c * 3 + 1];
        y2 += v * W3[c * 3 + 2];
    }
    float ys[3] = {y0, y1, y2};
    #pragma unroll
    for (int k = 0; k < 3; k++) {
        float y = tanhf(ys[k]);
        if (isnan(y)) y = 0.0f;
        y = fminf(fmaxf(y, -2.5f), 2.5f);
        out[((size_t)b * NV + n) * 3 + k] = V[n * 3 + k] + y;
    }
}

// ---------------- host driver ----------------
extern "C" void kernel_launch(void* const* d_in, const int* in_sizes, int n_in,
                              void* d_out, int out_size) {
    const float* feat  = (const float*)d_in[0];
    const float* verts = (const float*)d_in[1];
    const int*   eidx  = (const int*)d_in[2];
    int E = in_sizes[2] / 2;
    if (E > MAXE) E = MAXE;
    const int* esrc = eidx;
    const int* edst = eidx + E;
    const float* encW1 = (const float*)d_in[3];
    const float* encb1 = (const float*)d_in[4];
    const float* encW2 = (const float*)d_in[5];
    const float* encb2 = (const float*)d_in[6];
    const float* gW[6] = {(const float*)d_in[7],  (const float*)d_in[9],
                          (const float*)d_in[11], (const float*)d_in[13],
                          (const float*)d_in[15], (const float*)d_in[17]};
    const float* gb[6] = {(const float*)d_in[8],  (const float*)d_in[10],
                          (const float*)d_in[12], (const float*)d_in[14],
                          (const float*)d_in[16], (const float*)d_in[18]};
    const float* hW1 = (const float*)d_in[19];
    const float* hb1 = (const float*)d_in[20];
    const float* hW2 = (const float*)d_in[21];
    const float* hb2 = (const float*)d_in[22];
    const float* hW3 = (const float*)d_in[23];
    const float* hb3 = (const float*)d_in[24];

    float *bufA, *bufB, *bufC;
    __nv_bfloat16 *wthi, *wtlo;
    cudaGetSymbolAddress((void**)&bufA, g_bufA);
    cudaGetSymbolAddress((void**)&bufB, g_bufB);
    cudaGetSymbolAddress((void**)&bufC, g_bufC);
    cudaGetSymbolAddress((void**)&wthi, g_WThi);
    cudaGetSymbolAddress((void**)&wtlo, g_WTlo);

    cudaFuncSetAttribute(k_mma_gemm, cudaFuncAttributeMaxDynamicSharedMemorySize, GEMM_SMEM);

    const int woff[9] = {0, 32768, 65536, 196608, 720896, 1245184, 1376256, 1409024, 1425408};
    const int wk[9]   = {256, 128, 256, 512, 1024, 512, 256, 128, 128};
    const int wn[9]   = {128, 256, 512, 1024, 512, 256, 128, 128, 64};
    const float* wptr[9] = {encW2, gW[0], gW[1], gW[2], gW[3], gW[4], gW[5], hW1, hW2};

    auto gemm = [&](const float* A, int li, float* C, const float* bias, int relu) {
        dim3 grid((wn[li] + 127) / 128, MTILES);
        k_mma_gemm<<<grid, 512, GEMM_SMEM>>>(A, wthi + woff[li], wtlo + woff[li], C,
                                             wk[li], wn[li], bias, relu);
    };

    // launch order: #4 = first big GEMM (ncu capture window)
    k_prep<<<1, 1024>>>(feat, encW1, encb1);                                  // 1
    k_wsplit<<<(wn[0] * wk[0] + 255) / 256, 256>>>(wptr[0], wk[0], wn[0],
                                                   wthi + woff[0], wtlo + woff[0]); // 2
    k_enc1<<<MROWS, 256>>>(verts, encW1);                                     // 3
    gemm(bufA, 0, bufB, encb2, 1);                                            // 4 (profiled)

    for (int li = 1; li < 9; li++)
        k_wsplit<<<(wn[li] * wk[li] + 255) / 256, 256>>>(wptr[li], wk[li], wn[li],
                                                         wthi + woff[li], wtlo + woff[li]);
    k_zero<<<(NV + 255) / 256, 256>>>();
    k_count<<<(E + 255) / 256, 256>>>(edst, E);
    k_scan<<<1, 1024>>>();
    k_dinv<<<(NV + 255) / 256, 256>>>();
    k_fill<<<(E + 255) / 256, 256>>>(esrc, edst, E);
    k_sort<<<(NV + 255) / 256, 256>>>();

    // g1..g3: aggregate-then-GEMM (Cin < Cout); bias+relu fused in GEMM
    k_agg<<<dim3(1, NV), 128>>>(bufB, bufC, (const float*)0, 128, 0);
    gemm(bufC, 1, bufA, gb[0], 1);
    k_agg<<<dim3(2, NV), 128>>>(bufA, bufC, (const float*)0, 256, 0);
    gemm(bufC, 2, bufB, gb[1], 1);
    k_agg<<<dim3(4, NV), 128>>>(bufB, bufC, (const float*)0, 512, 0);
    gemm(bufC, 3, bufA, gb[2], 1);
    // g4..g6: GEMM-then-aggregate (Cout < Cin); bias+relu fused in aggregate
    gemm(bufA, 4, bufC, (const float*)0, 0);
    k_agg<<<dim3(4, NV), 128>>>(bufC, bufB, gb[3], 512, 1);
    gemm(bufB, 5, bufC, (const float*)0, 0);
    k_agg<<<dim3(2, NV), 128>>>(bufC, bufA, gb[4], 256, 1);
    gemm(bufA, 6, bufC, (const float*)0, 0);
    k_agg<<<dim3(1, NV), 128>>>(bufC, bufB, gb[5], 128, 1);
    // head
    gemm(bufB, 7, bufA, hb1, 1);
    gemm(bufA, 8, bufC, hb2, 1);
    k_head3<<<(MROWS + 255) / 256, 256>>>(bufC, hW3, hb3, verts, (float*)d_out);
}